// round 15
// baseline (speedup 1.0000x reference)
#include <cuda_runtime.h>

// DetectionLayer: x (B, 255, 76, 76) f32  ->  out (B, 3*76*76, 85) f32
// out[b, a*G*G + s, c] = f_c( x[b, a*85+c, s] ),  s = gy*G + gx
//   c==0: (sigmoid(v)+gx)*8     c==1: (sigmoid(v)+gy)*8
//   c==2: exp(v)*anchor_w[a]    c==3: exp(v)*anchor_h[a]
//   c>=4: sigmoid(v)
// (stride = 608/76 = 8; (anchor/stride)*stride == raw anchor)
//
// Design converged (R0-R13 theory audits): smem tile per (b,a,gy) row;
// conflict-free STS (lane-delta 85 = 21 mod 32) and LDS.128 (linear copy);
// coalesced scalar LDG along s; STG.128 on contiguous output slab;
// 64 warps/SM. Expected DRAM-bound at ~70%+ of peak. Frozen pending
// first successful bench; predictions pre-registered.

constexpr int G   = 76;
constexpr int GG  = G * G;      // 5776
constexpr int CPA = 85;         // 80 cls + 5
constexpr int NA  = 3;
constexpr int TS  = G;          // one gy row per tile

__device__ __forceinline__ float fsig(float v) {
    return 1.0f / (1.0f + __expf(-v));
}

__global__ __launch_bounds__(256)
void det_kernel(const float* __restrict__ x,
                const float* __restrict__ anchors,
                float* __restrict__ out)
{
    __shared__ float sm[TS * CPA];    // [s][c] unpadded; TRANSFORMED values

    const int bid   = blockIdx.x;
    const int tile  = bid % G;        // gy
    const int plane = bid / G;        // b*NA + a
    const int a     = plane % NA;

    const float aw = anchors[2 * a];
    const float ah = anchors[2 * a + 1];
    const float gy = (float)tile;

    // ---- Load + transform: i = c*76 + s, scalar LDG (coalesced along s) ----
    // A warp spans <= 2 channels -> per-channel branch nearly convergent.
    const float* xb = x + (size_t)plane * (CPA * GG) + tile * G;
    constexpr int NE = CPA * TS;            // 6460 elements
    #pragma unroll 8
    for (int i = threadIdx.x; i < NE; i += 256) {
        int c = i / TS;
        int s = i - c * TS;
        float v = __ldcs(xb + (size_t)c * GG + s);
        float t;
        if (c == 0)      t = (fsig(v) + (float)s) * 8.0f;
        else if (c == 1) t = (fsig(v) + gy) * 8.0f;
        else if (c == 2) t = __expf(v) * aw;
        else if (c == 3) t = __expf(v) * ah;
        else             t = fsig(v);
        sm[s * CPA + c] = t;                // lane-delta 85 -> conflict-free
    }
    __syncthreads();

    // ---- Store: linear copy, LDS.128 conflict-free, STG.128 coalesced ----
    float4* ob = reinterpret_cast<float4*>(
        out + ((size_t)plane * GG + tile * G) * CPA);
    const float4* sb = reinterpret_cast<const float4*>(sm);
    constexpr int W4 = TS * CPA / 4;        // 1615
    #pragma unroll 4
    for (int i = threadIdx.x; i < W4; i += 256) {
        __stcs(ob + i, sb[i]);
    }
}

extern "C" void kernel_launch(void* const* d_in, const int* in_sizes, int n_in,
                              void* d_out, int out_size)
{
    const float* x       = (const float*)d_in[0];
    const float* anchors = (const float*)d_in[1];
    float* out           = (float*)d_out;

    int B = in_sizes[0] / (NA * CPA * GG);   // 32 for the bench shape
    det_kernel<<<B * NA * G, 256>>>(x, anchors, out);
}

// round 16
// speedup vs baseline: 1.5222x; 1.5222x over previous
#include <cuda_runtime.h>

// DetectionLayer: x (B, 255, 76, 76) f32  ->  out (B, 3*76*76, 85) f32
// out[b, a*G*G + s, c] = f_c( x[b, a*85+c, s] ),  s = gy*G + gx
// R15 measurement: scalar-LDG version was issue/ALU-bound (issue 63%, alu 41%,
// DRAM only 33%). This version: LDG.128 (4x fewer loads, 4x less index math,
// channel uniform per float4), transform fused at load, unpadded [s][c] smem
// (STS 4-way conflict accepted: L1 pipe had 3x headroom), linear LDS.128 store.

constexpr int G   = 76;
constexpr int GG  = G * G;      // 5776
constexpr int CPA = 85;         // 80 cls + 5
constexpr int NA  = 3;
constexpr int TS  = G;          // one gy row per tile

__device__ __forceinline__ float fsig(float v) {
    return 1.0f / (1.0f + __expf(-v));
}

__global__ __launch_bounds__(256)
void det_kernel(const float* __restrict__ x,
                const float* __restrict__ anchors,
                float* __restrict__ out)
{
    __shared__ float sm[TS * CPA];    // [s][c] unpadded; TRANSFORMED values

    const int bid   = blockIdx.x;
    const int tile  = bid % G;        // gy
    const int plane = bid / G;        // b*NA + a
    const int a     = plane % NA;

    const float aw = anchors[2 * a];
    const float ah = anchors[2 * a + 1];
    const float gy = (float)tile;

    // ---- Load + transform: i = c*19 + q, LDG.128 along s ----
    // All 4 elements of a float4 share one channel c -> branch uniform per thread.
    const float* xb = x + (size_t)plane * (CPA * GG) + tile * G;
    constexpr int Q  = TS / 4;              // 19 float4 per channel row
    constexpr int L4 = CPA * Q;             // 1615
    #pragma unroll 4
    for (int i = threadIdx.x; i < L4; i += 256) {
        int c = i / Q;
        int q = i - c * Q;
        float4 v = __ldcs(reinterpret_cast<const float4*>(xb + (size_t)c * GG) + q);
        float r[4] = {v.x, v.y, v.z, v.w};
        if (c >= 4) {
            #pragma unroll
            for (int j = 0; j < 4; j++) r[j] = fsig(r[j]);
        } else if (c == 0) {
            float gx = (float)(q * 4);
            r[0] = (fsig(r[0]) + gx)        * 8.0f;
            r[1] = (fsig(r[1]) + gx + 1.0f) * 8.0f;
            r[2] = (fsig(r[2]) + gx + 2.0f) * 8.0f;
            r[3] = (fsig(r[3]) + gx + 3.0f) * 8.0f;
        } else if (c == 1) {
            #pragma unroll
            for (int j = 0; j < 4; j++) r[j] = (fsig(r[j]) + gy) * 8.0f;
        } else {                            // c == 2 or 3
            float an = (c == 2) ? aw : ah;
            #pragma unroll
            for (int j = 0; j < 4; j++) r[j] = __expf(r[j]) * an;
        }
        // scatter to [s][c]: 4 STS, stride 85 between j's (4-way lane conflict, OK)
        float* d = sm + (q * 4) * CPA + c;
        d[0]       = r[0];
        d[CPA]     = r[1];
        d[2 * CPA] = r[2];
        d[3 * CPA] = r[3];
    }
    __syncthreads();

    // ---- Store: linear copy, LDS.128 conflict-free, STG.128 coalesced ----
    float4* ob = reinterpret_cast<float4*>(
        out + ((size_t)plane * GG + tile * G) * CPA);
    const float4* sb = reinterpret_cast<const float4*>(sm);
    constexpr int W4 = TS * CPA / 4;        // 1615
    #pragma unroll 4
    for (int i = threadIdx.x; i < W4; i += 256) {
        __stcs(ob + i, sb[i]);
    }
}

extern "C" void kernel_launch(void* const* d_in, const int* in_sizes, int n_in,
                              void* d_out, int out_size)
{
    const float* x       = (const float*)d_in[0];
    const float* anchors = (const float*)d_in[1];
    float* out           = (float*)d_out;

    int B = in_sizes[0] / (NA * CPA * GG);   // 32 for the bench shape
    det_kernel<<<B * NA * G, 256>>>(x, anchors, out);
}